// round 5
// baseline (speedup 1.0000x reference)
#include <cuda_runtime.h>
#include <math.h>

// ---------------- problem constants ----------------
#define NS 32768   // samples
#define DD 1024    // feat dim
#define HH 4096    // hidden dim

// ---------------- scratch (alloc-free rule: __device__ globals) ----------------
__device__ float g_S[DD * DD];            // 4 MB   feature scores
__device__ float g_P[DD * DD];            // 4 MB   softmax scores
__device__ float g_attn[(size_t)NS * DD]; // 128 MB attention output
__device__ float g_hid[(size_t)NS * HH];  // 512 MB MLP hidden (also split-K scratch)

// ---------------- tiled fp32 GEMM ----------------
// C[M,N] = epi( sum_k A(m,k) * B(k,n) )
//  TA=false: A stored [M,K] row-major ; TA=true: A stored [K,M] row-major
//  TB=false: B stored [K,N] row-major ; TB=true: B stored [N,K] row-major
//  EPI: 0 = plain store, 1 = split-K slab store (offset by z*M*N),
//       2 = bias + relu, 3 = bias
#define BM 128
#define BN 128
#define BK 16
#define TM 8
#define TN 8
#define PAD 4

template<bool TA, bool TB, int EPI>
__global__ __launch_bounds__(256)
void gemm_kernel(const float* __restrict__ A, const float* __restrict__ B,
                 const float* __restrict__ bias, float* __restrict__ C,
                 int M, int N, int K, int kPer)
{
    __shared__ float As[BK][BM + PAD];
    __shared__ float Bs[BK][BN + PAD];

    const int tid = threadIdx.x;
    const int bm0 = blockIdx.y * BM;
    const int bn0 = blockIdx.x * BN;
    const int kBeg = blockIdx.z * kPer;
    const int kEnd = kBeg + kPer;

    float acc[TM][TN];
    #pragma unroll
    for (int i = 0; i < TM; i++)
        #pragma unroll
        for (int j = 0; j < TN; j++) acc[i][j] = 0.f;

    const int tx = tid & 15;   // 0..15 -> N direction
    const int ty = tid >> 4;   // 0..15 -> M direction

    for (int k0 = kBeg; k0 < kEnd; k0 += BK) {
        // ---- load A tile into As[kk][mm] ----
        if (TA) {
            // A[k, m]: rows are contiguous in m -> vectorized direct store
            #pragma unroll
            for (int r = 0; r < 2; r++) {
                int lin = tid + 256 * r;          // 512 float4s
                int kk  = lin >> 5;               // /32
                int m4  = lin & 31;
                float4 v = *(const float4*)&A[(size_t)(k0 + kk) * M + bm0 + m4 * 4];
                *(float4*)&As[kk][m4 * 4] = v;
            }
        } else {
            // A[m, k]: load 16 contiguous k per row, transpose into smem
            #pragma unroll
            for (int r = 0; r < 2; r++) {
                int lin = tid + 256 * r;
                int mm  = lin >> 2;               // /4
                int k4  = lin & 3;
                float4 v = *(const float4*)&A[(size_t)(bm0 + mm) * K + k0 + k4 * 4];
                As[k4 * 4 + 0][mm] = v.x;
                As[k4 * 4 + 1][mm] = v.y;
                As[k4 * 4 + 2][mm] = v.z;
                As[k4 * 4 + 3][mm] = v.w;
            }
        }
        // ---- load B tile into Bs[kk][nn] ----
        if (TB) {
            // B[n, k]
            #pragma unroll
            for (int r = 0; r < 2; r++) {
                int lin = tid + 256 * r;
                int nn  = lin >> 2;
                int k4  = lin & 3;
                float4 v = *(const float4*)&B[(size_t)(bn0 + nn) * K + k0 + k4 * 4];
                Bs[k4 * 4 + 0][nn] = v.x;
                Bs[k4 * 4 + 1][nn] = v.y;
                Bs[k4 * 4 + 2][nn] = v.z;
                Bs[k4 * 4 + 3][nn] = v.w;
            }
        } else {
            // B[k, n]
            #pragma unroll
            for (int r = 0; r < 2; r++) {
                int lin = tid + 256 * r;
                int kk  = lin >> 5;
                int n4  = lin & 31;
                float4 v = *(const float4*)&B[(size_t)(k0 + kk) * N + bn0 + n4 * 4];
                *(float4*)&Bs[kk][n4 * 4] = v;
            }
        }
        __syncthreads();

        #pragma unroll
        for (int kk = 0; kk < BK; kk++) {
            float a[TM], b[TN];
            #pragma unroll
            for (int i = 0; i < TM; i++) a[i] = As[kk][ty * TM + i];
            #pragma unroll
            for (int j = 0; j < TN; j++) b[j] = Bs[kk][tx * TN + j];
            #pragma unroll
            for (int i = 0; i < TM; i++)
                #pragma unroll
                for (int j = 0; j < TN; j++)
                    acc[i][j] += a[i] * b[j];
        }
        __syncthreads();
    }

    // ---- epilogue ----
    const size_t slab = (EPI == 1) ? (size_t)blockIdx.z * (size_t)M * (size_t)N : 0;
    #pragma unroll
    for (int i = 0; i < TM; i++) {
        int m = bm0 + ty * TM + i;
        #pragma unroll
        for (int j = 0; j < TN; j++) {
            int n = bn0 + tx * TN + j;
            size_t off = (size_t)m * N + n;
            float v = acc[i][j];
            if (EPI == 0)      C[off] = v;
            else if (EPI == 1) C[slab + off] = v;
            else if (EPI == 2) C[off] = fmaxf(v + bias[n], 0.f);
            else               C[off] = v + bias[n];
        }
    }
}

// ---------------- deterministic split-K reduction (8 slabs) ----------------
__global__ void reduce8_kernel(const float* __restrict__ part, float* __restrict__ S)
{
    int i = blockIdx.x * blockDim.x + threadIdx.x;   // 0 .. DD*DD-1
    float s = 0.f;
    #pragma unroll
    for (int z = 0; z < 8; z++) s += part[(size_t)z * (DD * DD) + i];
    S[i] = s;
}

// ---------------- double-exp row softmax ----------------
// logit = exp(s - s*I/sqrt(D));  scores = softmax(logit, axis=-1)
__global__ void softmax_kernel(const float* __restrict__ S, float* __restrict__ P)
{
    const int row = blockIdx.x;       // 0..1023
    const int tid = threadIdx.x;      // 256 threads, 4 cols each
    __shared__ float red[256];

    float l[4];
    float mx = -1e30f;
    #pragma unroll
    for (int r = 0; r < 4; r++) {
        int col = tid + r * 256;
        float s = S[(size_t)row * DD + col];
        float scale = (col == row) ? (1.0f - 1.0f / 32.0f) : 1.0f;  // sqrt(1024)=32
        l[r] = expf(s * scale);       // this is "logit"
        mx = fmaxf(mx, l[r]);
    }
    red[tid] = mx;
    __syncthreads();
    for (int s = 128; s > 0; s >>= 1) {
        if (tid < s) red[tid] = fmaxf(red[tid], red[tid + s]);
        __syncthreads();
    }
    mx = red[0];
    __syncthreads();

    float e[4], sum = 0.f;
    #pragma unroll
    for (int r = 0; r < 4; r++) { e[r] = expf(l[r] - mx); sum += e[r]; }
    red[tid] = sum;
    __syncthreads();
    for (int s = 128; s > 0; s >>= 1) {
        if (tid < s) red[tid] += red[tid + s];
        __syncthreads();
    }
    float inv = 1.0f / red[0];
    #pragma unroll
    for (int r = 0; r < 4; r++) {
        int col = tid + r * 256;
        P[(size_t)row * DD + col] = e[r] * inv;
    }
}

// ---------------- launch ----------------
extern "C" void kernel_launch(void* const* d_in, const int* in_sizes, int n_in,
                              void* d_out, int out_size)
{
    const float* q   = (const float*)d_in[0];
    const float* k   = (const float*)d_in[1];
    const float* v   = (const float*)d_in[2];
    const float* wq1 = (const float*)d_in[3];
    const float* bq1 = (const float*)d_in[4];
    const float* wq2 = (const float*)d_in[5];
    const float* bq2 = (const float*)d_in[6];
    const float* wk1 = (const float*)d_in[7];
    const float* bk1 = (const float*)d_in[8];
    const float* wk2 = (const float*)d_in[9];
    const float* bk2 = (const float*)d_in[10];
    float* out = (float*)d_out;

    float *S, *P, *attn, *hid;
    cudaGetSymbolAddress((void**)&S,    g_S);
    cudaGetSymbolAddress((void**)&P,    g_P);
    cudaGetSymbolAddress((void**)&attn, g_attn);
    cudaGetSymbolAddress((void**)&hid,  g_hid);

    // 1) S = Q^T K  [1024,1024], split-K=8 deterministic slabs into g_hid scratch
    gemm_kernel<true, false, 1><<<dim3(DD / BN, DD / BM, 8), 256>>>(
        q, k, nullptr, hid, DD, DD, NS, NS / 8);
    reduce8_kernel<<<(DD * DD) / 256, 256>>>(hid, S);

    // 2) double-exp softmax -> P
    softmax_kernel<<<DD, 256>>>(S, P);

    // 3) attn = V @ P^T  [32768,1024]
    gemm_kernel<false, true, 0><<<dim3(DD / BN, NS / BM, 1), 256>>>(
        v, P, nullptr, attn, NS, DD, DD, DD);

    // 4) query branch MLP
    gemm_kernel<false, false, 2><<<dim3(HH / BN, NS / BM, 1), 256>>>(
        attn, wq1, bq1, hid, NS, HH, DD, DD);
    gemm_kernel<false, false, 3><<<dim3(DD / BN, NS / BM, 1), 256>>>(
        hid, wq2, bq2, out, NS, DD, HH, HH);

    // 5) key branch MLP
    gemm_kernel<false, false, 2><<<dim3(HH / BN, NS / BM, 1), 256>>>(
        attn, wk1, bk1, hid, NS, HH, DD, DD);
    gemm_kernel<false, false, 3><<<dim3(DD / BN, NS / BM, 1), 256>>>(
        hid, wk2, bk2, out + (size_t)NS * DD, NS, DD, HH, HH);
}

// round 7
// speedup vs baseline: 5.7503x; 5.7503x over previous
#include <cuda_runtime.h>
#include <stdint.h>
#include <math.h>

// ---------------- problem constants ----------------
#define NS 32768
#define DD 1024
#define HH 4096

// ---------------- GEMM tiling ----------------
#define BM 128
#define BN 128
#define BK 16
#define NSTAGE 3
#define SPLITZ 16
#define ROWF 20                       // floats per smem row (16 + 4 pad)
#define ATILE (BM * ROWF * 4)         // 10240 B
#define STAGE_BYTES (2 * ATILE)       // 20480 B
#define SMEM_BYTES (NSTAGE * STAGE_BYTES)  // 61440 B

// ---------------- scratch (__device__ globals; no allocs) ----------------
__device__ float g_S[DD * DD];
__device__ float g_P[DD * DD];
__device__ float g_attn[(size_t)NS * DD];
__device__ float g_hid[(size_t)NS * HH];     // also split-K slabs
__device__ float g_qt[(size_t)DD * NS];
__device__ float g_kt[(size_t)DD * NS];
__device__ float g_vt[(size_t)NS * DD];
__device__ float g_w1qt[(size_t)HH * DD];
__device__ float g_w2qt[(size_t)DD * HH];
__device__ float g_w1kt[(size_t)HH * DD];
__device__ float g_w2kt[(size_t)DD * HH];

// ---------------- helpers ----------------
__device__ __forceinline__ uint32_t smem_u32(const void* p) {
    uint32_t a;
    asm("{ .reg .u64 t; cvta.to.shared.u64 t, %1; cvt.u32.u64 %0, t; }" : "=r"(a) : "l"(p));
    return a;
}
__device__ __forceinline__ float rtf(float x) {   // unbiased round-to-nearest tf32
    uint32_t r;
    asm("cvt.rna.tf32.f32 %0, %1;" : "=r"(r) : "f"(x));
    return __uint_as_float(r);
}
__device__ __forceinline__ void cp16(uint32_t dst, const void* src) {
    asm volatile("cp.async.cg.shared.global [%0], [%1], 16;" :: "r"(dst), "l"(src));
}
#define CP_COMMIT() asm volatile("cp.async.commit_group;" ::: "memory")
#define CP_WAIT1()  asm volatile("cp.async.wait_group 1;" ::: "memory")

__device__ __forceinline__ void mma1688(float* d, const uint32_t* a, const uint32_t* b) {
    asm volatile(
        "mma.sync.aligned.m16n8k8.row.col.f32.tf32.tf32.f32 "
        "{%0,%1,%2,%3}, {%4,%5,%6,%7}, {%8,%9}, {%0,%1,%2,%3};"
        : "+f"(d[0]), "+f"(d[1]), "+f"(d[2]), "+f"(d[3])
        : "r"(a[0]), "r"(a[1]), "r"(a[2]), "r"(a[3]), "r"(b[0]), "r"(b[1]));
}

// load one 128-row x 16-col (K-major) fp32 panel into padded smem rows
__device__ __forceinline__ void load_panel(const float* __restrict__ G, int row0,
                                           int K, int k0, uint32_t sdst, int tid) {
    #pragma unroll
    for (int r = 0; r < 2; r++) {
        int lin = tid + 256 * r;          // 0..511
        int m   = lin >> 2;
        int k4  = lin & 3;
        cp16(sdst + (uint32_t)(m * (ROWF * 4) + k4 * 16),
             G + (size_t)(row0 + m) * K + k0 + k4 * 4);
    }
}

// ---------------- tf32 mma.sync GEMM: C = epi(A[M,K] @ B[N,K]^T) ----------------
// EPI: 0 = tf32-round store, 1 = split-K slab store (raw), 2 = bias+relu+round, 3 = bias
template<int EPI>
__global__ void __launch_bounds__(256)
tc_gemm(const float* __restrict__ A, const float* __restrict__ B,
        const float* __restrict__ bias, float* __restrict__ C,
        int M, int N, int K, int kPer)
{
    extern __shared__ char smem[];
    const uint32_t sbase = smem_u32(smem);
    const int tid = threadIdx.x;
    const int wid = tid >> 5, lane = tid & 31;
    const int g = lane >> 2, tig = lane & 3;       // groupID / thread-in-group
    const int wm = wid & 3, wn = wid >> 2;         // 4 (M) x 2 (N) warps
    const int m0 = blockIdx.y * BM;
    const int n0 = blockIdx.x * BN;
    const int kBeg = blockIdx.z * kPer;
    const int T = kPer / BK;

    float acc[2][8][4];
    #pragma unroll
    for (int mt = 0; mt < 2; mt++)
        #pragma unroll
        for (int nt = 0; nt < 8; nt++)
            #pragma unroll
            for (int e = 0; e < 4; e++) acc[mt][nt][e] = 0.f;

    // prologue: stages 0,1
    #pragma unroll
    for (int p = 0; p < 2; p++) {
        if (p < T) {
            uint32_t buf = sbase + p * STAGE_BYTES;
            load_panel(A, m0, K, kBeg + p * BK, buf, tid);
            load_panel(B, n0, K, kBeg + p * BK, buf + ATILE, tid);
        }
        CP_COMMIT();
    }

    for (int t = 0; t < T; t++) {
        const int s = t % NSTAGE;
        const uint32_t buf = sbase + s * STAGE_BYTES;
        const uint32_t* Au = (const uint32_t*)(smem + (size_t)s * STAGE_BYTES);
        const uint32_t* Bu = (const uint32_t*)(smem + (size_t)s * STAGE_BYTES + ATILE);
        (void)buf;

        CP_WAIT1();          // stage t's group landed (only t+1 may be pending)
        __syncthreads();     // also: everyone done reading stage (t-1)%3

        #pragma unroll
        for (int ks = 0; ks < 2; ks++) {
            const int kb = ks * 8;
            uint32_t af[2][4];
            #pragma unroll
            for (int mt = 0; mt < 2; mt++) {
                int row = wm * 32 + mt * 16 + g;
                af[mt][0] = Au[row * ROWF + kb + tig];
                af[mt][1] = Au[(row + 8) * ROWF + kb + tig];
                af[mt][2] = Au[row * ROWF + kb + tig + 4];
                af[mt][3] = Au[(row + 8) * ROWF + kb + tig + 4];
            }
            #pragma unroll
            for (int nt = 0; nt < 8; nt++) {
                int col = wn * 64 + nt * 8 + g;
                uint32_t bf[2];
                bf[0] = Bu[col * ROWF + kb + tig];
                bf[1] = Bu[col * ROWF + kb + tig + 4];
                mma1688(acc[0][nt], af[0], bf);
                mma1688(acc[1][nt], af[1], bf);
            }
        }

        const int tn = t + 2;
        if (tn < T) {
            uint32_t nbuf = sbase + (tn % NSTAGE) * STAGE_BYTES;
            load_panel(A, m0, K, kBeg + tn * BK, nbuf, tid);
            load_panel(B, n0, K, kBeg + tn * BK, nbuf + ATILE, tid);
        }
        CP_COMMIT();         // one group per iter keeps accounting exact
    }

    // ---- epilogue ----
    const size_t slab = (EPI == 1) ? (size_t)blockIdx.z * (size_t)M * (size_t)N : 0;
    #pragma unroll
    for (int mt = 0; mt < 2; mt++) {
        const int row = m0 + wm * 32 + mt * 16 + g;
        #pragma unroll
        for (int nt = 0; nt < 8; nt++) {
            const int col = n0 + wn * 64 + nt * 8 + tig * 2;
            float c0 = acc[mt][nt][0], c1 = acc[mt][nt][1];
            float c2 = acc[mt][nt][2], c3 = acc[mt][nt][3];
            if (EPI == 2 || EPI == 3) {
                float2 bv = *(const float2*)&bias[col];
                c0 += bv.x; c1 += bv.y; c2 += bv.x; c3 += bv.y;
            }
            if (EPI == 2) {
                c0 = rtf(fmaxf(c0, 0.f)); c1 = rtf(fmaxf(c1, 0.f));
                c2 = rtf(fmaxf(c2, 0.f)); c3 = rtf(fmaxf(c3, 0.f));
            } else if (EPI == 0) {
                c0 = rtf(c0); c1 = rtf(c1); c2 = rtf(c2); c3 = rtf(c3);
            }
            *(float2*)&C[slab + (size_t)row * N + col]       = make_float2(c0, c1);
            *(float2*)&C[slab + (size_t)(row + 8) * N + col] = make_float2(c2, c3);
        }
    }
}

// ---------------- aux kernels ----------------
__global__ void transpose_round(const float* __restrict__ in, float* __restrict__ out,
                                int R, int C)
{
    __shared__ float t[32][33];
    const int c0 = blockIdx.x * 32, r0 = blockIdx.y * 32;
    const int x = threadIdx.x, y = threadIdx.y;
    #pragma unroll
    for (int i = 0; i < 32; i += 8)
        t[y + i][x] = in[(size_t)(r0 + y + i) * C + c0 + x];
    __syncthreads();
    #pragma unroll
    for (int i = 0; i < 32; i += 8)
        out[(size_t)(c0 + y + i) * R + r0 + x] = rtf(t[x][y + i]);
}

__global__ void round_copy4(const float4* __restrict__ in, float4* __restrict__ out,
                            size_t n4)
{
    size_t i = (size_t)blockIdx.x * blockDim.x + threadIdx.x;
    if (i < n4) {
        float4 v = in[i];
        v.x = rtf(v.x); v.y = rtf(v.y); v.z = rtf(v.z); v.w = rtf(v.w);
        out[i] = v;
    }
}

__global__ void reduceZ_kernel(const float* __restrict__ part, float* __restrict__ S)
{
    int i = blockIdx.x * blockDim.x + threadIdx.x;
    float s = 0.f;
    #pragma unroll
    for (int z = 0; z < SPLITZ; z++) s += part[(size_t)z * (DD * DD) + i];
    S[i] = s;
}

__global__ void softmax_kernel(const float* __restrict__ S, float* __restrict__ P)
{
    const int row = blockIdx.x;
    const int tid = threadIdx.x;
    __shared__ float red[256];

    float l[4];
    float mx = -1e30f;
    #pragma unroll
    for (int r = 0; r < 4; r++) {
        int col = tid + r * 256;
        float s = S[(size_t)row * DD + col];
        float scale = (col == row) ? (1.0f - 1.0f / 32.0f) : 1.0f;  // sqrt(1024)=32
        l[r] = expf(s * scale);
        mx = fmaxf(mx, l[r]);
    }
    red[tid] = mx;
    __syncthreads();
    for (int s = 128; s > 0; s >>= 1) {
        if (tid < s) red[tid] = fmaxf(red[tid], red[tid + s]);
        __syncthreads();
    }
    mx = red[0];
    __syncthreads();

    float e[4], sum = 0.f;
    #pragma unroll
    for (int r = 0; r < 4; r++) { e[r] = expf(l[r] - mx); sum += e[r]; }
    red[tid] = sum;
    __syncthreads();
    for (int s = 128; s > 0; s >>= 1) {
        if (tid < s) red[tid] += red[tid + s];
        __syncthreads();
    }
    float inv = 1.0f / red[0];
    #pragma unroll
    for (int r = 0; r < 4; r++) {
        int col = tid + r * 256;
        P[(size_t)row * DD + col] = rtf(e[r] * inv);
    }
}

// ---------------- launch ----------------
extern "C" void kernel_launch(void* const* d_in, const int* in_sizes, int n_in,
                              void* d_out, int out_size)
{
    const float* q   = (const float*)d_in[0];
    const float* k   = (const float*)d_in[1];
    const float* v   = (const float*)d_in[2];
    const float* wq1 = (const float*)d_in[3];
    const float* bq1 = (const float*)d_in[4];
    const float* wq2 = (const float*)d_in[5];
    const float* bq2 = (const float*)d_in[6];
    const float* wk1 = (const float*)d_in[7];
    const float* bk1 = (const float*)d_in[8];
    const float* wk2 = (const float*)d_in[9];
    const float* bk2 = (const float*)d_in[10];
    float* out = (float*)d_out;

    float *S, *P, *attn, *hid, *qt, *kt, *vt, *w1q, *w2q, *w1k, *w2k;
    cudaGetSymbolAddress((void**)&S,    g_S);
    cudaGetSymbolAddress((void**)&P,    g_P);
    cudaGetSymbolAddress((void**)&attn, g_attn);
    cudaGetSymbolAddress((void**)&hid,  g_hid);
    cudaGetSymbolAddress((void**)&qt,   g_qt);
    cudaGetSymbolAddress((void**)&kt,   g_kt);
    cudaGetSymbolAddress((void**)&vt,   g_vt);
    cudaGetSymbolAddress((void**)&w1q,  g_w1qt);
    cudaGetSymbolAddress((void**)&w2q,  g_w2qt);
    cudaGetSymbolAddress((void**)&w1k,  g_w1kt);
    cudaGetSymbolAddress((void**)&w2k,  g_w2kt);

    cudaFuncSetAttribute(tc_gemm<0>, cudaFuncAttributeMaxDynamicSharedMemorySize, SMEM_BYTES);
    cudaFuncSetAttribute(tc_gemm<1>, cudaFuncAttributeMaxDynamicSharedMemorySize, SMEM_BYTES);
    cudaFuncSetAttribute(tc_gemm<2>, cudaFuncAttributeMaxDynamicSharedMemorySize, SMEM_BYTES);
    cudaFuncSetAttribute(tc_gemm<3>, cudaFuncAttributeMaxDynamicSharedMemorySize, SMEM_BYTES);

    dim3 tb(32, 8);

    // 0) operand prep: transpose + tf32 round-to-nearest
    transpose_round<<<dim3(DD / 32, NS / 32), tb>>>(q, qt, NS, DD);
    transpose_round<<<dim3(DD / 32, NS / 32), tb>>>(k, kt, NS, DD);
    round_copy4<<<(int)((size_t)NS * DD / 4 / 256), 256>>>(
        (const float4*)v, (float4*)vt, (size_t)NS * DD / 4);
    transpose_round<<<dim3(HH / 32, DD / 32), tb>>>(wq1, w1q, DD, HH);
    transpose_round<<<dim3(DD / 32, HH / 32), tb>>>(wq2, w2q, HH, DD);
    transpose_round<<<dim3(HH / 32, DD / 32), tb>>>(wk1, w1k, DD, HH);
    transpose_round<<<dim3(DD / 32, HH / 32), tb>>>(wk2, w2k, HH, DD);

    // 1) S = Q^T K : A=qt[DD,NS], B=kt[DD,NS], split-K=16 slabs into hid scratch
    tc_gemm<1><<<dim3(DD / BN, DD / BM, SPLITZ), 256, SMEM_BYTES>>>(
        qt, kt, nullptr, hid, DD, DD, NS, NS / SPLITZ);
    reduceZ_kernel<<<(DD * DD) / 256, 256>>>(hid, S);

    // 2) softmax -> P (tf32-rounded)
    softmax_kernel<<<DD, 256>>>(S, P);

    // 3) attn = V @ P^T : A=vt[NS,DD], B=P[DD,DD]
    tc_gemm<0><<<dim3(DD / BN, NS / BM, 1), 256, SMEM_BYTES>>>(
        vt, P, nullptr, attn, NS, DD, DD, DD);

    // 4) query branch
    tc_gemm<2><<<dim3(HH / BN, NS / BM, 1), 256, SMEM_BYTES>>>(
        attn, w1q, bq1, hid, NS, HH, DD, DD);
    tc_gemm<3><<<dim3(DD / BN, NS / BM, 1), 256, SMEM_BYTES>>>(
        hid, w2q, bq2, out, NS, DD, HH, HH);

    // 5) key branch
    tc_gemm<2><<<dim3(HH / BN, NS / BM, 1), 256, SMEM_BYTES>>>(
        attn, w1k, bk1, hid, NS, HH, DD, DD);
    tc_gemm<3><<<dim3(DD / BN, NS / BM, 1), 256, SMEM_BYTES>>>(
        hid, w2k, bk2, out + (size_t)NS * DD, NS, DD, HH, HH);
}

// round 11
// speedup vs baseline: 10.2822x; 1.7881x over previous
#include <cuda_runtime.h>
#include <cuda_fp16.h>
#include <stdint.h>
#include <math.h>

// ---------------- problem constants ----------------
#define NS 32768
#define DD 1024
#define HH 4096

// ---------------- GEMM tiling ----------------
#define BM 256
#define BN 128
#define BKH 32                  // halfs of K per stage (2 x k16 mma steps)
#define NSTAGE 4
#define SPLITZ 16
#define ROWW 20                 // 32-bit words per padded smem row (16 data + 4 pad)
#define ATILE (BM * ROWW * 4)   // 20480 B
#define BTILE (BN * ROWW * 4)   // 10240 B
#define STAGE_BYTES (ATILE + BTILE)        // 30720 B
#define SMEM_BYTES (NSTAGE * STAGE_BYTES)  // 122880 B

// ---------------- scratch (__device__ globals; no allocs) ----------------
__device__ float  g_S[DD * DD];                     // fp32 scores
__device__ float  g_slab[(size_t)SPLITZ * DD * DD]; // fp32 split-K slabs (64 MB)
__device__ __half g_P[DD * DD];
__device__ __half g_attn[(size_t)NS * DD];
__device__ __half g_hid[(size_t)NS * HH];
__device__ __half g_qt[(size_t)DD * NS];
__device__ __half g_kt[(size_t)DD * NS];
__device__ __half g_vt[(size_t)NS * DD];
__device__ __half g_w1q[(size_t)HH * DD];
__device__ __half g_w2q[(size_t)DD * HH];
__device__ __half g_w1k[(size_t)HH * DD];
__device__ __half g_w2k[(size_t)DD * HH];

// ---------------- helpers ----------------
__device__ __forceinline__ uint32_t smem_u32(const void* p) {
    uint32_t a;
    asm("{ .reg .u64 t; cvta.to.shared.u64 t, %1; cvt.u32.u64 %0, t; }" : "=r"(a) : "l"(p));
    return a;
}
__device__ __forceinline__ void cp16(uint32_t dst, const void* src) {
    asm volatile("cp.async.cg.shared.global [%0], [%1], 16;" :: "r"(dst), "l"(src));
}
#define CP_COMMIT() asm volatile("cp.async.commit_group;" ::: "memory")
#define CP_WAIT2()  asm volatile("cp.async.wait_group 2;" ::: "memory")

__device__ __forceinline__ void mma16816(float* d, const uint32_t* a,
                                         uint32_t b0, uint32_t b1) {
    asm volatile(
        "mma.sync.aligned.m16n8k16.row.col.f32.f16.f16.f32 "
        "{%0,%1,%2,%3}, {%4,%5,%6,%7}, {%8,%9}, {%0,%1,%2,%3};"
        : "+f"(d[0]), "+f"(d[1]), "+f"(d[2]), "+f"(d[3])
        : "r"(a[0]), "r"(a[1]), "r"(a[2]), "r"(a[3]), "r"(b0), "r"(b1));
}

// load NROWS x 32-half (K-major) fp16 panel into padded smem rows (80B stride)
template<int NROWS>
__device__ __forceinline__ void load_panel(const __half* __restrict__ G, int row0,
                                           int ldK, int k0, uint32_t sdst, int tid) {
    #pragma unroll
    for (int i = 0; i < NROWS / 64; i++) {          // NROWS*4 segs / 256 thr
        int idx = tid + i * 256;
        int row = idx >> 2;
        int seg = idx & 3;                          // 4 x 16B (8 halfs) per row
        cp16(sdst + (uint32_t)(row * (ROWW * 4) + seg * 16),
             G + (size_t)(row0 + row) * ldK + k0 + seg * 8);
    }
}

// ---------------- fp16 mma.sync GEMM: C = epi(A[M,K] @ B[N,K]^T) ----------------
// EPI: 0 = fp16 store, 1 = fp32 split-K slab store, 2 = bias+relu -> fp16,
//      3 = bias -> fp32
template<int EPI>
__global__ void __launch_bounds__(256, 1)
tc_gemm(const __half* __restrict__ A, const __half* __restrict__ B,
        const float* __restrict__ bias, void* __restrict__ Cv,
        int M, int N, int K, int kPer)
{
    extern __shared__ char smem[];
    const uint32_t sbase = smem_u32(smem);
    const int tid = threadIdx.x;
    const int wid = tid >> 5, lane = tid & 31;
    const int g = lane >> 2, tig = lane & 3;
    const int wm = wid & 3, wn = wid >> 2;          // 4(M) x 2(N) warps -> 64x64 each
    const int m0 = blockIdx.y * BM;
    const int n0 = blockIdx.x * BN;
    const int kBeg = blockIdx.z * kPer;
    const int T = kPer / BKH;

    float acc[4][8][4];
    #pragma unroll
    for (int mt = 0; mt < 4; mt++)
        #pragma unroll
        for (int nt = 0; nt < 8; nt++)
            #pragma unroll
            for (int e = 0; e < 4; e++) acc[mt][nt][e] = 0.f;

    // prologue: stages 0..2
    #pragma unroll
    for (int p = 0; p < NSTAGE - 1; p++) {
        if (p < T) {
            uint32_t buf = sbase + p * STAGE_BYTES;
            load_panel<BM>(A, m0, K, kBeg + p * BKH, buf, tid);
            load_panel<BN>(B, n0, K, kBeg + p * BKH, buf + ATILE, tid);
        }
        CP_COMMIT();
    }

    for (int t = 0; t < T; t++) {
        const int s = t % NSTAGE;
        const uint32_t* Au = (const uint32_t*)(smem + (size_t)s * STAGE_BYTES);
        const uint32_t* Bu = (const uint32_t*)(smem + (size_t)s * STAGE_BYTES + ATILE);

        CP_WAIT2();          // stage t landed (t+1, t+2 may be in flight)
        __syncthreads();     // all warps: visibility + done reading stage t-1

        #pragma unroll
        for (int ks = 0; ks < 2; ks++) {            // 2 x k16 per stage
            const int kb = ks * 8;
            uint32_t af[4][4];
            #pragma unroll
            for (int mt = 0; mt < 4; mt++) {
                int row = wm * 64 + mt * 16 + g;
                af[mt][0] = Au[row * ROWW + kb + tig];
                af[mt][1] = Au[(row + 8) * ROWW + kb + tig];
                af[mt][2] = Au[row * ROWW + kb + tig + 4];
                af[mt][3] = Au[(row + 8) * ROWW + kb + tig + 4];
            }
            #pragma unroll
            for (int nt = 0; nt < 8; nt++) {
                int col = wn * 64 + nt * 8 + g;
                uint32_t b0 = Bu[col * ROWW + kb + tig];
                uint32_t b1 = Bu[col * ROWW + kb + tig + 4];
                #pragma unroll
                for (int mt = 0; mt < 4; mt++)
                    mma16816(acc[mt][nt], af[mt], b0, b1);
            }
        }

        const int tn = t + NSTAGE - 1;
        if (tn < T) {
            uint32_t nbuf = sbase + (tn % NSTAGE) * STAGE_BYTES;
            load_panel<BM>(A, m0, K, kBeg + tn * BKH, nbuf, tid);
            load_panel<BN>(B, n0, K, kBeg + tn * BKH, nbuf + ATILE, tid);
        }
        CP_COMMIT();         // exactly one group per iter keeps accounting exact
    }

    // ---- epilogue ----
    const size_t slab = (EPI == 1) ? (size_t)blockIdx.z * (size_t)M * (size_t)N : 0;
    float*  Cf = (float*)Cv;
    __half* Ch = (__half*)Cv;

    #pragma unroll
    for (int mt = 0; mt < 4; mt++) {
        const int row = m0 + wm * 64 + mt * 16 + g;
        #pragma unroll
        for (int nt = 0; nt < 8; nt++) {
            const int col = n0 + wn * 64 + nt * 8 + tig * 2;
            float c0 = acc[mt][nt][0], c1 = acc[mt][nt][1];
            float c2 = acc[mt][nt][2], c3 = acc[mt][nt][3];
            if (EPI == 2 || EPI == 3) {
                float2 bv = *(const float2*)&bias[col];
                c0 += bv.x; c1 += bv.y; c2 += bv.x; c3 += bv.y;
            }
            if (EPI == 2) {
                c0 = fmaxf(c0, 0.f); c1 = fmaxf(c1, 0.f);
                c2 = fmaxf(c2, 0.f); c3 = fmaxf(c3, 0.f);
            }
            if (EPI == 0 || EPI == 2) {
                *(__half2*)&Ch[(size_t)row * N + col]       = __floats2half2_rn(c0, c1);
                *(__half2*)&Ch[(size_t)(row + 8) * N + col] = __floats2half2_rn(c2, c3);
            } else {
                *(float2*)&Cf[slab + (size_t)row * N + col]       = make_float2(c0, c1);
                *(float2*)&Cf[slab + (size_t)(row + 8) * N + col] = make_float2(c2, c3);
            }
        }
    }
}

// ---------------- aux kernels ----------------
// transpose fp32 [R,C] -> fp16 [C,R]
__global__ void transpose_h(const float* __restrict__ in, __half* __restrict__ out,
                            int R, int C)
{
    __shared__ float t[32][33];
    const int c0 = blockIdx.x * 32, r0 = blockIdx.y * 32;
    const int x = threadIdx.x, y = threadIdx.y;
    #pragma unroll
    for (int i = 0; i < 32; i += 8)
        t[y + i][x] = in[(size_t)(r0 + y + i) * C + c0 + x];
    __syncthreads();
    #pragma unroll
    for (int i = 0; i < 32; i += 8)
        out[(size_t)(c0 + y + i) * R + r0 + x] = __float2half_rn(t[x][y + i]);
}

// fp32 -> fp16 copy
__global__ void copy_h(const float4* __restrict__ in, __half2* __restrict__ out,
                       size_t n4)
{
    size_t i = (size_t)blockIdx.x * blockDim.x + threadIdx.x;
    if (i < n4) {
        float4 v = in[i];
        out[i * 2]     = __floats2half2_rn(v.x, v.y);
        out[i * 2 + 1] = __floats2half2_rn(v.z, v.w);
    }
}

__global__ void reduceZ_kernel(const float* __restrict__ part, float* __restrict__ S)
{
    int i = blockIdx.x * blockDim.x + threadIdx.x;
    float s = 0.f;
    #pragma unroll
    for (int z = 0; z < SPLITZ; z++) s += part[(size_t)z * (DD * DD) + i];
    S[i] = s;
}

// double-exp row softmax; fp16 output (feeds attn GEMM as B)
__global__ void softmax_kernel(const float* __restrict__ S, __half* __restrict__ P)
{
    const int row = blockIdx.x;
    const int tid = threadIdx.x;
    __shared__ float red[256];

    float l[4];
    float mx = -1e30f;
    #pragma unroll
    for (int r = 0; r < 4; r++) {
        int col = tid + r * 256;
        float s = S[(size_t)row * DD + col];
        float scale = (col == row) ? (1.0f - 1.0f / 32.0f) : 1.0f;  // sqrt(1024)=32
        l[r] = expf(s * scale);
        mx = fmaxf(mx, l[r]);
    }
    red[tid] = mx;
    __syncthreads();
    for (int s = 128; s > 0; s >>= 1) {
        if (tid < s) red[tid] = fmaxf(red[tid], red[tid + s]);
        __syncthreads();
    }
    mx = red[0];
    __syncthreads();

    float e[4], sum = 0.f;
    #pragma unroll
    for (int r = 0; r < 4; r++) { e[r] = expf(l[r] - mx); sum += e[r]; }
    red[tid] = sum;
    __syncthreads();
    for (int s = 128; s > 0; s >>= 1) {
        if (tid < s) red[tid] += red[tid + s];
        __syncthreads();
    }
    float inv = 1.0f / red[0];
    #pragma unroll
    for (int r = 0; r < 4; r++) {
        int col = tid + r * 256;
        P[(size_t)row * DD + col] = __float2half_rn(e[r] * inv);
    }
}

// ---------------- launch ----------------
extern "C" void kernel_launch(void* const* d_in, const int* in_sizes, int n_in,
                              void* d_out, int out_size)
{
    const float* q   = (const float*)d_in[0];
    const float* k   = (const float*)d_in[1];
    const float* v   = (const float*)d_in[2];
    const float* wq1 = (const float*)d_in[3];
    const float* bq1 = (const float*)d_in[4];
    const float* wq2 = (const float*)d_in[5];
    const float* bq2 = (const float*)d_in[6];
    const float* wk1 = (const float*)d_in[7];
    const float* bk1 = (const float*)d_in[8];
    const float* wk2 = (const float*)d_in[9];
    const float* bk2 = (const float*)d_in[10];
    float* out = (float*)d_out;

    float *S, *slab;
    __half *P, *attn, *hid, *qt, *kt, *vt, *w1q, *w2q, *w1k, *w2k;
    cudaGetSymbolAddress((void**)&S,    g_S);
    cudaGetSymbolAddress((void**)&slab, g_slab);
    cudaGetSymbolAddress((void**)&P,    g_P);
    cudaGetSymbolAddress((void**)&attn, g_attn);
    cudaGetSymbolAddress((void**)&hid,  g_hid);
    cudaGetSymbolAddress((void**)&qt,   g_qt);
    cudaGetSymbolAddress((void**)&kt,   g_kt);
    cudaGetSymbolAddress((void**)&vt,   g_vt);
    cudaGetSymbolAddress((void**)&w1q,  g_w1q);
    cudaGetSymbolAddress((void**)&w2q,  g_w2q);
    cudaGetSymbolAddress((void**)&w1k,  g_w1k);
    cudaGetSymbolAddress((void**)&w2k,  g_w2k);

    cudaFuncSetAttribute(tc_gemm<0>, cudaFuncAttributeMaxDynamicSharedMemorySize, SMEM_BYTES);
    cudaFuncSetAttribute(tc_gemm<1>, cudaFuncAttributeMaxDynamicSharedMemorySize, SMEM_BYTES);
    cudaFuncSetAttribute(tc_gemm<2>, cudaFuncAttributeMaxDynamicSharedMemorySize, SMEM_BYTES);
    cudaFuncSetAttribute(tc_gemm<3>, cudaFuncAttributeMaxDynamicSharedMemorySize, SMEM_BYTES);

    dim3 tb(32, 8);

    // 0) operand prep: transpose / copy with fp16 round-to-nearest
    transpose_h<<<dim3(DD / 32, NS / 32), tb>>>(q, qt, NS, DD);
    transpose_h<<<dim3(DD / 32, NS / 32), tb>>>(k, kt, NS, DD);
    copy_h<<<(int)((size_t)NS * DD / 4 / 256), 256>>>(
        (const float4*)v, (__half2*)vt, (size_t)NS * DD / 4);
    transpose_h<<<dim3(HH / 32, DD / 32), tb>>>(wq1, w1q, DD, HH);
    transpose_h<<<dim3(DD / 32, HH / 32), tb>>>(wq2, w2q, HH, DD);
    transpose_h<<<dim3(HH / 32, DD / 32), tb>>>(wk1, w1k, DD, HH);
    transpose_h<<<dim3(DD / 32, HH / 32), tb>>>(wk2, w2k, HH, DD);

    // 1) S = Q^T K : A=qt[DD,NS], B=kt[DD,NS], split-K=16 fp32 slabs
    tc_gemm<1><<<dim3(DD / BN, DD / BM, SPLITZ), 256, SMEM_BYTES>>>(
        qt, kt, nullptr, slab, DD, DD, NS, NS / SPLITZ);
    reduceZ_kernel<<<(DD * DD) / 256, 256>>>(slab, S);

    // 2) softmax -> P (fp16)
    softmax_kernel<<<DD, 256>>>(S, P);

    // 3) attn = V @ P^T : A=vt[NS,DD], B=P[DD,DD] -> fp16
    tc_gemm<0><<<dim3(DD / BN, NS / BM, 1), 256, SMEM_BYTES>>>(
        vt, P, nullptr, attn, NS, DD, DD, DD);

    // 4) query branch
    tc_gemm<2><<<dim3(HH / BN, NS / BM, 1), 256, SMEM_BYTES>>>(
        attn, w1q, bq1, hid, NS, HH, DD, DD);
    tc_gemm<3><<<dim3(DD / BN, NS / BM, 1), 256, SMEM_BYTES>>>(
        hid, w2q, bq2, out, NS, DD, HH, HH);

    // 5) key branch
    tc_gemm<2><<<dim3(HH / BN, NS / BM, 1), 256, SMEM_BYTES>>>(
        attn, w1k, bk1, hid, NS, HH, DD, DD);
    tc_gemm<3><<<dim3(DD / BN, NS / BM, 1), 256, SMEM_BYTES>>>(
        hid, w2k, bk2, out + (size_t)NS * DD, NS, DD, HH, HH);
}

// round 13
// speedup vs baseline: 12.8106x; 1.2459x over previous
#include <cuda_runtime.h>
#include <cuda_fp16.h>
#include <stdint.h>
#include <math.h>

// ---------------- problem constants ----------------
#define NS 32768
#define DD 1024
#define HH 4096

// ---------------- GEMM tiling ----------------
#define BM 256
#define BN 128
#define BKH 64                  // halfs of K per stage (4 x k16 mma steps)
#define NSTAGE 3
#define SPLITZ 16
#define ROWW 36                 // 32-bit words per padded smem row (32 data + 4 pad)
#define ROWB (ROWW * 4)         // 144 bytes
#define ATILE (BM * ROWB)       // 36864 B
#define BTILE (BN * ROWB)       // 18432 B
#define STAGE_BYTES (ATILE + BTILE)        // 55296 B
#define SMEM_BYTES (NSTAGE * STAGE_BYTES)  // 165888 B

// ---------------- scratch (__device__ globals; no allocs) ----------------
__device__ float  g_S[DD * DD];                     // fp32 scores
__device__ float  g_slab[(size_t)SPLITZ * DD * DD]; // fp32 split-K slabs
__device__ __half g_P[DD * DD];
__device__ __half g_attn[(size_t)NS * DD];
__device__ __half g_hid[(size_t)NS * HH];
__device__ __half g_qt[(size_t)DD * NS];
__device__ __half g_kt[(size_t)DD * NS];
__device__ __half g_vt[(size_t)NS * DD];
__device__ __half g_w1q[(size_t)HH * DD];
__device__ __half g_w2q[(size_t)DD * HH];
__device__ __half g_w1k[(size_t)HH * DD];
__device__ __half g_w2k[(size_t)DD * HH];

// ---------------- helpers ----------------
__device__ __forceinline__ uint32_t smem_u32(const void* p) {
    uint32_t a;
    asm("{ .reg .u64 t; cvta.to.shared.u64 t, %1; cvt.u32.u64 %0, t; }" : "=r"(a) : "l"(p));
    return a;
}
__device__ __forceinline__ void cp16(uint32_t dst, const void* src) {
    asm volatile("cp.async.cg.shared.global [%0], [%1], 16;" :: "r"(dst), "l"(src));
}
#define CP_COMMIT() asm volatile("cp.async.commit_group;" ::: "memory")
#define CP_WAIT1()  asm volatile("cp.async.wait_group 1;" ::: "memory")

#define LDSM4(r, a) \
    asm volatile("ldmatrix.sync.aligned.m8n8.x4.shared.b16 {%0,%1,%2,%3}, [%4];" \
        : "=r"((r)[0]), "=r"((r)[1]), "=r"((r)[2]), "=r"((r)[3]) : "r"(a))

__device__ __forceinline__ void mma16816(float* d, const uint32_t* a,
                                         uint32_t b0, uint32_t b1) {
    asm volatile(
        "mma.sync.aligned.m16n8k16.row.col.f32.f16.f16.f32 "
        "{%0,%1,%2,%3}, {%4,%5,%6,%7}, {%8,%9}, {%0,%1,%2,%3};"
        : "+f"(d[0]), "+f"(d[1]), "+f"(d[2]), "+f"(d[3])
        : "r"(a[0]), "r"(a[1]), "r"(a[2]), "r"(a[3]), "r"(b0), "r"(b1));
}

// load NROWS x 64-half (K-major) fp16 panel into padded smem rows (144B stride)
template<int NROWS>
__device__ __forceinline__ void load_panel(const __half* __restrict__ G, int row0,
                                           int ldK, int k0, uint32_t sdst, int tid) {
    #pragma unroll
    for (int i = 0; i < NROWS / 32; i++) {          // NROWS*8 segs / 256 thr
        int idx = tid + i * 256;
        int row = idx >> 3;
        int seg = idx & 7;                          // 8 x 16B (8 halfs) per row
        cp16(sdst + (uint32_t)(row * ROWB + seg * 16),
             G + (size_t)(row0 + row) * ldK + k0 + seg * 8);
    }
}

// ---------------- fp16 mma.sync GEMM: C = epi(A[M,K] @ B[N,K]^T) ----------------
// EPI: 0 = fp16 store, 1 = fp32 split-K slab store, 2 = bias+relu -> fp16,
//      3 = bias -> fp32
template<int EPI>
__global__ void __launch_bounds__(256, 1)
tc_gemm(const __half* __restrict__ A, const __half* __restrict__ B,
        const float* __restrict__ bias, void* __restrict__ Cv,
        int M, int N, int K, int kPer)
{
    extern __shared__ char smem[];
    const uint32_t sbase = smem_u32(smem);
    const int tid = threadIdx.x;
    const int wid = tid >> 5, lane = tid & 31;
    const int g = lane >> 2, tig = lane & 3;
    const int wm = wid & 3, wn = wid >> 2;          // 4(M) x 2(N) warps -> 64x64 each
    const int m0 = blockIdx.y * BM;
    const int n0 = blockIdx.x * BN;
    const int kBeg = blockIdx.z * kPer;
    const int T = kPer / BKH;

    // per-lane ldmatrix byte offsets (relative to stage A / B bases)
    //  A: matrices {r0-7 k0-7, r8-15 k0-7, r0-7 k8-15, r8-15 k8-15}
    const uint32_t aOff = (uint32_t)((wm * 64 + (lane & 15)) * ROWB
                                     + ((lane >> 4) << 4));
    //  B: matrices {n0-7 k0-7, n0-7 k8-15, n8-15 k0-7, n8-15 k8-15}
    const uint32_t bOff = (uint32_t)((wn * 64 + ((lane >> 4) & 1) * 8 + (lane & 7)) * ROWB
                                     + (((lane >> 3) & 1) << 4));

    float acc[4][8][4];
    #pragma unroll
    for (int mt = 0; mt < 4; mt++)
        #pragma unroll
        for (int nt = 0; nt < 8; nt++)
            #pragma unroll
            for (int e = 0; e < 4; e++) acc[mt][nt][e] = 0.f;

    // prologue: stages 0,1
    #pragma unroll
    for (int p = 0; p < NSTAGE - 1; p++) {
        uint32_t buf = sbase + p * STAGE_BYTES;
        load_panel<BM>(A, m0, K, kBeg + p * BKH, buf, tid);
        load_panel<BN>(B, n0, K, kBeg + p * BKH, buf + ATILE, tid);
        CP_COMMIT();
    }

    for (int t = 0; t < T; t++) {
        const int s = t % NSTAGE;
        const uint32_t sA = sbase + s * STAGE_BYTES;
        const uint32_t sB = sA + ATILE;

        CP_WAIT1();          // stage t landed (only stage t+1 in flight)
        __syncthreads();     // visibility + all warps done reading stage (t-1)%3

        #pragma unroll
        for (int ks = 0; ks < 4; ks++) {            // 4 x k16 per stage
            const uint32_t kbb = ks * 32;           // 8 words = 32 bytes
            uint32_t af[4][4], bf[4][4];
            #pragma unroll
            for (int mt = 0; mt < 4; mt++)
                LDSM4(af[mt], sA + aOff + mt * 16 * ROWB + kbb);
            #pragma unroll
            for (int nt2 = 0; nt2 < 4; nt2++)
                LDSM4(bf[nt2], sB + bOff + nt2 * 16 * ROWB + kbb);
            #pragma unroll
            for (int nt2 = 0; nt2 < 4; nt2++)
                #pragma unroll
                for (int h = 0; h < 2; h++) {
                    const int nt = nt2 * 2 + h;
                    #pragma unroll
                    for (int mt = 0; mt < 4; mt++)
                        mma16816(acc[mt][nt], af[mt], bf[nt2][h * 2], bf[nt2][h * 2 + 1]);
                }
        }

        const int tn = t + NSTAGE - 1;
        if (tn < T) {
            uint32_t nbuf = sbase + (tn % NSTAGE) * STAGE_BYTES;
            load_panel<BM>(A, m0, K, kBeg + tn * BKH, nbuf, tid);
            load_panel<BN>(B, n0, K, kBeg + tn * BKH, nbuf + ATILE, tid);
        }
        CP_COMMIT();         // exactly one group per iter keeps accounting exact
    }

    // ---- epilogue (layout identical to validated R8 kernel) ----
    const size_t slab = (EPI == 1) ? (size_t)blockIdx.z * (size_t)M * (size_t)N : 0;
    float*  Cf = (float*)Cv;
    __half* Ch = (__half*)Cv;

    #pragma unroll
    for (int mt = 0; mt < 4; mt++) {
        const int row = m0 + wm * 64 + mt * 16 + g;
        #pragma unroll
        for (int nt = 0; nt < 8; nt++) {
            const int col = n0 + wn * 64 + nt * 8 + tig * 2;
            float c0 = acc[mt][nt][0], c1 = acc[mt][nt][1];
            float c2 = acc[mt][nt][2], c3 = acc[mt][nt][3];
            if (EPI == 2 || EPI == 3) {
                float2 bv = *(const float2*)&bias[col];
                c0 += bv.x; c1 += bv.y; c2 += bv.x; c3 += bv.y;
            }
            if (EPI == 2) {
                c0 = fmaxf(c0, 0.f); c1 = fmaxf(c1, 0.f);
                c2 = fmaxf(c2, 0.f); c3 = fmaxf(c3, 0.f);
            }
            if (EPI == 0 || EPI == 2) {
                *(__half2*)&Ch[(size_t)row * N + col]       = __floats2half2_rn(c0, c1);
                *(__half2*)&Ch[(size_t)(row + 8) * N + col] = __floats2half2_rn(c2, c3);
            } else {
                *(float2*)&Cf[slab + (size_t)row * N + col]       = make_float2(c0, c1);
                *(float2*)&Cf[slab + (size_t)(row + 8) * N + col] = make_float2(c2, c3);
            }
        }
    }
}

// ---------------- aux kernels ----------------
// transpose fp32 [R,C] -> fp16 [C,R]
__global__ void transpose_h(const float* __restrict__ in, __half* __restrict__ out,
                            int R, int C)
{
    __shared__ float t[32][33];
    const int c0 = blockIdx.x * 32, r0 = blockIdx.y * 32;
    const int x = threadIdx.x, y = threadIdx.y;
    #pragma unroll
    for (int i = 0; i < 32; i += 8)
        t[y + i][x] = in[(size_t)(r0 + y + i) * C + c0 + x];
    __syncthreads();
    #pragma unroll
    for (int i = 0; i < 32; i += 8)
        out[(size_t)(c0 + y + i) * R + r0 + x] = __float2half_rn(t[x][y + i]);
}

// fp32 -> fp16 copy
__global__ void copy_h(const float4* __restrict__ in, __half2* __restrict__ out,
                       size_t n4)
{
    size_t i = (size_t)blockIdx.x * blockDim.x + threadIdx.x;
    if (i < n4) {
        float4 v = in[i];
        out[i * 2]     = __floats2half2_rn(v.x, v.y);
        out[i * 2 + 1] = __floats2half2_rn(v.z, v.w);
    }
}

__global__ void reduceZ_kernel(const float* __restrict__ part, float* __restrict__ S)
{
    int i = blockIdx.x * blockDim.x + threadIdx.x;
    float s = 0.f;
    #pragma unroll
    for (int z = 0; z < SPLITZ; z++) s += part[(size_t)z * (DD * DD) + i];
    S[i] = s;
}

// double-exp row softmax; fp16 output (feeds attn GEMM as B)
__global__ void softmax_kernel(const float* __restrict__ S, __half* __restrict__ P)
{
    const int row = blockIdx.x;
    const int tid = threadIdx.x;
    __shared__ float red[256];

    float l[4];
    float mx = -1e30f;
    #pragma unroll
    for (int r = 0; r < 4; r++) {
        int col = tid + r * 256;
        float s = S[(size_t)row * DD + col];
        float scale = (col == row) ? (1.0f - 1.0f / 32.0f) : 1.0f;  // sqrt(1024)=32
        l[r] = expf(s * scale);
        mx = fmaxf(mx, l[r]);
    }
    red[tid] = mx;
    __syncthreads();
    for (int s = 128; s > 0; s >>= 1) {
        if (tid < s) red[tid] = fmaxf(red[tid], red[tid + s]);
        __syncthreads();
    }
    mx = red[0];
    __syncthreads();

    float e[4], sum = 0.f;
    #pragma unroll
    for (int r = 0; r < 4; r++) { e[r] = expf(l[r] - mx); sum += e[r]; }
    red[tid] = sum;
    __syncthreads();
    for (int s = 128; s > 0; s >>= 1) {
        if (tid < s) red[tid] += red[tid + s];
        __syncthreads();
    }
    float inv = 1.0f / red[0];
    #pragma unroll
    for (int r = 0; r < 4; r++) {
        int col = tid + r * 256;
        P[(size_t)row * DD + col] = __float2half_rn(e[r] * inv);
    }
}

// ---------------- launch ----------------
extern "C" void kernel_launch(void* const* d_in, const int* in_sizes, int n_in,
                              void* d_out, int out_size)
{
    const float* q   = (const float*)d_in[0];
    const float* k   = (const float*)d_in[1];
    const float* v   = (const float*)d_in[2];
    const float* wq1 = (const float*)d_in[3];
    const float* bq1 = (const float*)d_in[4];
    const float* wq2 = (const float*)d_in[5];
    const float* bq2 = (const float*)d_in[6];
    const float* wk1 = (const float*)d_in[7];
    const float* bk1 = (const float*)d_in[8];
    const float* wk2 = (const float*)d_in[9];
    const float* bk2 = (const float*)d_in[10];
    float* out = (float*)d_out;

    float *S, *slab;
    __half *P, *attn, *hid, *qt, *kt, *vt, *w1q, *w2q, *w1k, *w2k;
    cudaGetSymbolAddress((void**)&S,    g_S);
    cudaGetSymbolAddress((void**)&slab, g_slab);
    cudaGetSymbolAddress((void**)&P,    g_P);
    cudaGetSymbolAddress((void**)&attn, g_attn);
    cudaGetSymbolAddress((void**)&hid,  g_hid);
    cudaGetSymbolAddress((void**)&qt,   g_qt);
    cudaGetSymbolAddress((void**)&kt,   g_kt);
    cudaGetSymbolAddress((void**)&vt,   g_vt);
    cudaGetSymbolAddress((void**)&w1q,  g_w1q);
    cudaGetSymbolAddress((void**)&w2q,  g_w2q);
    cudaGetSymbolAddress((void**)&w1k,  g_w1k);
    cudaGetSymbolAddress((void**)&w2k,  g_w2k);

    cudaFuncSetAttribute(tc_gemm<0>, cudaFuncAttributeMaxDynamicSharedMemorySize, SMEM_BYTES);
    cudaFuncSetAttribute(tc_gemm<1>, cudaFuncAttributeMaxDynamicSharedMemorySize, SMEM_BYTES);
    cudaFuncSetAttribute(tc_gemm<2>, cudaFuncAttributeMaxDynamicSharedMemorySize, SMEM_BYTES);
    cudaFuncSetAttribute(tc_gemm<3>, cudaFuncAttributeMaxDynamicSharedMemorySize, SMEM_BYTES);

    dim3 tb(32, 8);

    // 0) operand prep: transpose / copy with fp16 round-to-nearest
    transpose_h<<<dim3(DD / 32, NS / 32), tb>>>(q, qt, NS, DD);
    transpose_h<<<dim3(DD / 32, NS / 32), tb>>>(k, kt, NS, DD);
    copy_h<<<(int)((size_t)NS * DD / 4 / 256), 256>>>(
        (const float4*)v, (__half2*)vt, (size_t)NS * DD / 4);
    transpose_h<<<dim3(HH / 32, DD / 32), tb>>>(wq1, w1q, DD, HH);
    transpose_h<<<dim3(DD / 32, HH / 32), tb>>>(wq2, w2q, HH, DD);
    transpose_h<<<dim3(HH / 32, DD / 32), tb>>>(wk1, w1k, DD, HH);
    transpose_h<<<dim3(DD / 32, HH / 32), tb>>>(wk2, w2k, HH, DD);

    // 1) S = Q^T K : A=qt[DD,NS], B=kt[DD,NS], split-K=16 fp32 slabs
    tc_gemm<1><<<dim3(DD / BN, DD / BM, SPLITZ), 256, SMEM_BYTES>>>(
        qt, kt, nullptr, slab, DD, DD, NS, NS / SPLITZ);
    reduceZ_kernel<<<(DD * DD) / 256, 256>>>(slab, S);

    // 2) softmax -> P (fp16)
    softmax_kernel<<<DD, 256>>>(S, P);

    // 3) attn = V @ P^T : A=vt[NS,DD], B=P[DD,DD] -> fp16
    tc_gemm<0><<<dim3(DD / BN, NS / BM, 1), 256, SMEM_BYTES>>>(
        vt, P, nullptr, attn, NS, DD, DD, DD);

    // 4) query branch
    tc_gemm<2><<<dim3(HH / BN, NS / BM, 1), 256, SMEM_BYTES>>>(
        attn, w1q, bq1, hid, NS, HH, DD, DD);
    tc_gemm<3><<<dim3(DD / BN, NS / BM, 1), 256, SMEM_BYTES>>>(
        hid, w2q, bq2, out, NS, DD, HH, HH);

    // 5) key branch
    tc_gemm<2><<<dim3(HH / BN, NS / BM, 1), 256, SMEM_BYTES>>>(
        attn, w1k, bk1, hid, NS, HH, DD, DD);
    tc_gemm<3><<<dim3(DD / BN, NS / BM, 1), 256, SMEM_BYTES>>>(
        hid, w2k, bk2, out + (size_t)NS * DD, NS, DD, HH, HH);
}